// round 6
// baseline (speedup 1.0000x reference)
#include <cuda_runtime.h>
#include <cuda_bf16.h>
#include <math.h>
#include <stdint.h>

#define BROWS 8192
#define HIDK  1024
#define HH    64
#define QQ    99
#define NI    640
#define NTOT  704          // 64 + 640 real output cols
#define NTOTP 768          // padded to 6 x 128
#define NOUT  (HH*QQ)      // 6336

// ---------------- scratch (allocation-free rule: __device__ globals) -------
__device__ float          g_med[BROWS * HH];      // 2 MB
__device__ float          g_inc[BROWS * NI];      // 20 MB
__device__ __nv_bfloat16  g_xb [BROWS * HIDK];    // 16 MB  x in bf16
__device__ __nv_bfloat16  g_wt [NTOTP * HIDK];    // 1.5 MB [Wm|Wi|0]^T, n-major rows

// ---------------- helpers ---------------------------------------------------
__device__ __forceinline__ uint32_t smem_u32(const void* p) {
    uint32_t a;
    asm("{ .reg .u64 t; cvta.to.shared.u64 t, %1; cvt.u32.u64 %0, t; }" : "=r"(a) : "l"(p));
    return a;
}
__device__ __forceinline__ void cp_async16(uint32_t saddr, const void* gptr) {
    asm volatile("cp.async.cg.shared.global [%0], [%1], 16;" :: "r"(saddr), "l"(gptr));
}
__device__ __forceinline__ void cp_commit() { asm volatile("cp.async.commit_group;"); }
template <int N>
__device__ __forceinline__ void cp_wait() { asm volatile("cp.async.wait_group %0;" :: "n"(N)); }

__device__ __forceinline__ void ldmx4(uint32_t& r0, uint32_t& r1, uint32_t& r2, uint32_t& r3,
                                      uint32_t addr) {
    asm volatile("ldmatrix.sync.aligned.m8n8.x4.shared.b16 {%0,%1,%2,%3}, [%4];"
                 : "=r"(r0), "=r"(r1), "=r"(r2), "=r"(r3) : "r"(addr));
}
__device__ __forceinline__ void mma16(float c[4], const uint32_t a[4], const uint32_t b[2]) {
    asm volatile(
        "mma.sync.aligned.m16n8k16.row.col.f32.bf16.bf16.f32 "
        "{%0,%1,%2,%3}, {%4,%5,%6,%7}, {%8,%9}, {%0,%1,%2,%3};"
        : "+f"(c[0]), "+f"(c[1]), "+f"(c[2]), "+f"(c[3])
        : "r"(a[0]), "r"(a[1]), "r"(a[2]), "r"(a[3]), "r"(b[0]), "r"(b[1]));
}
__device__ __forceinline__ void mma8(float c[4], const uint32_t a[4], const uint32_t b[2]) {
    asm volatile(
        "mma.sync.aligned.m16n8k8.row.col.f32.tf32.tf32.f32 "
        "{%0,%1,%2,%3}, {%4,%5,%6,%7}, {%8,%9}, {%0,%1,%2,%3};"
        : "+f"(c[0]), "+f"(c[1]), "+f"(c[2]), "+f"(c[3])
        : "r"(a[0]), "r"(a[1]), "r"(a[2]), "r"(a[3]), "r"(b[0]), "r"(b[1]));
}
__device__ __forceinline__ unsigned f2tf(float f) {
    unsigned u;
    asm("cvt.rna.tf32.f32 %0, %1;" : "=r"(u) : "f"(f));
    return u;
}
__device__ __forceinline__ float softplusf(float v) {
    return fmaxf(v, 0.f) + log1pf(expf(-fabsf(v)));
}

// ---------------------------------------------------------------------------
// Prep: x (f32) -> g_xb (bf16)
// ---------------------------------------------------------------------------
__global__ __launch_bounds__(256) void cvt_x_kernel(const float* __restrict__ x) {
    const int i = blockIdx.x * 256 + threadIdx.x;          // float4 index
    float4 v = ((const float4*)x)[i];
    __nv_bfloat162 p0 = __floats2bfloat162_rn(v.x, v.y);
    __nv_bfloat162 p1 = __floats2bfloat162_rn(v.z, v.w);
    uint2 u;
    u.x = *(uint32_t*)&p0;
    u.y = *(uint32_t*)&p1;
    ((uint2*)g_xb)[i] = u;
}

// Prep: g_wt[n][k] = concat(Wm, Wi, zeros)^T as bf16  (one block per n)
__global__ __launch_bounds__(256) void cvt_w_kernel(const float* __restrict__ Wm,
                                                    const float* __restrict__ Wi) {
    const int n = blockIdx.x;
    __nv_bfloat16* dst = g_wt + (size_t)n * HIDK;
    if (n >= NTOT) {
        #pragma unroll
        for (int it = 0; it < 4; it++) dst[threadIdx.x + it * 256] = __float2bfloat16(0.f);
        return;
    }
    const float* src;
    int ld, c;
    if (n < HH) { src = Wm; ld = HH; c = n; } else { src = Wi; ld = NI; c = n - HH; }
    #pragma unroll
    for (int it = 0; it < 4; it++) {
        const int k = threadIdx.x + it * 256;
        dst[k] = __float2bfloat16(src[(size_t)k * ld + c]);
    }
}

// ---------------------------------------------------------------------------
// Kernel 1: bf16 mma.sync m16n8k16 GEMM. Tile 128x128, BK=64, cp.async 2-stage.
// 8 warps as 4(m) x 2(n); warp tile 32x64. grid (64, 6) over padded N=768.
// Epilogue routes cols: [0,64)->median(+bm), [64,704)->softplus(+bi), rest drop.
// ---------------------------------------------------------------------------
#define BM 128
#define BN 128
#define BK 64
#define ASTR 72                       // bf16 elems per smem row (+16B pad)
#define ABYTES (BM * ASTR * 2)        // 18432
#define BBYTES (BN * ASTR * 2)        // 18432
#define STAGE  (ABYTES + BBYTES)      // 36864
#define SMEMSZ (2 * STAGE)            // 73728
#define NKC (HIDK / BK)               // 16

__global__ __launch_bounds__(256, 2) void gemm_kernel(const float* __restrict__ bm,
                                                      const float* __restrict__ bi) {
    extern __shared__ char sm[];
    const uint32_t smb = smem_u32(sm);

    const int tid  = threadIdx.x;
    const int wid  = tid >> 5, lane = tid & 31;
    const int m0   = blockIdx.x * BM;
    const int n0   = blockIdx.y * BN;

    const int wm = (wid & 3) * 32;        // warp m offset
    const int wn = (wid >> 2) * 64;       // warp n offset

    const __nv_bfloat16* Abase = g_xb + (size_t)m0 * HIDK;
    const __nv_bfloat16* Bbase = g_wt + (size_t)n0 * HIDK;

    const int ar = tid >> 3, ac = (tid & 7) * 8;          // 16B per op, 4 reps each

    float acc[2][8][4];
    #pragma unroll
    for (int mt = 0; mt < 2; mt++)
      #pragma unroll
      for (int nt = 0; nt < 8; nt++)
        #pragma unroll
        for (int i = 0; i < 4; i++) acc[mt][nt][i] = 0.f;

    const int quad = lane >> 3, rin = lane & 7;
    const int a_row = wm + rin + (quad & 1) * 8;          // + mt*16
    const int a_kof = (quad >> 1) * 8;                    // + ks*16
    const int b_row = wn + rin + (quad >> 1) * 8;         // + p*16
    const int b_kof = (quad & 1) * 8;                     // + ks*16

    // prologue: stage chunk 0
    {
        #pragma unroll
        for (int i = 0; i < 4; i++)
            cp_async16(smb + (uint32_t)((ar + i * 32) * ASTR + ac) * 2,
                       Abase + (size_t)(ar + i * 32) * HIDK + ac);
        #pragma unroll
        for (int i = 0; i < 4; i++)
            cp_async16(smb + ABYTES + (uint32_t)((ar + i * 32) * ASTR + ac) * 2,
                       Bbase + (size_t)(ar + i * 32) * HIDK + ac);
        cp_commit();
    }

    for (int kc = 0; kc < NKC; kc++) {
        const int buf = kc & 1;
        const uint32_t sa  = smb + (buf ? STAGE : 0);
        const uint32_t sbB = sa + ABYTES;

        if (kc + 1 < NKC) {                                 // prefetch next chunk
            const uint32_t pa = smb + ((1 - buf) ? STAGE : 0);
            const __nv_bfloat16* Ag = Abase + (size_t)(kc + 1) * BK;
            const __nv_bfloat16* Bg = Bbase + (size_t)(kc + 1) * BK;
            #pragma unroll
            for (int i = 0; i < 4; i++)
                cp_async16(pa + (uint32_t)((ar + i * 32) * ASTR + ac) * 2,
                           Ag + (size_t)(ar + i * 32) * HIDK + ac);
            #pragma unroll
            for (int i = 0; i < 4; i++)
                cp_async16(pa + ABYTES + (uint32_t)((ar + i * 32) * ASTR + ac) * 2,
                           Bg + (size_t)(ar + i * 32) * HIDK + ac);
            cp_commit();
            cp_wait<1>();
        } else {
            cp_wait<0>();
        }
        __syncthreads();

        #pragma unroll
        for (int ks = 0; ks < 4; ks++) {
            uint32_t af[2][4], bf[4][4];
            #pragma unroll
            for (int mt = 0; mt < 2; mt++)
                ldmx4(af[mt][0], af[mt][1], af[mt][2], af[mt][3],
                      sa + (uint32_t)((a_row + mt * 16) * ASTR + ks * 16 + a_kof) * 2);
            #pragma unroll
            for (int p = 0; p < 4; p++)
                ldmx4(bf[p][0], bf[p][1], bf[p][2], bf[p][3],
                      sbB + (uint32_t)((b_row + p * 16) * ASTR + ks * 16 + b_kof) * 2);
            #pragma unroll
            for (int mt = 0; mt < 2; mt++)
              #pragma unroll
              for (int nt = 0; nt < 8; nt++)
                mma16(acc[mt][nt], af[mt], &bf[nt >> 1][(nt & 1) * 2]);
        }
        __syncthreads();
    }

    // epilogue
    const int g = lane >> 2, tg = lane & 3;
    #pragma unroll
    for (int mt = 0; mt < 2; mt++) {
      #pragma unroll
      for (int nt = 0; nt < 8; nt++) {
        #pragma unroll
        for (int hf = 0; hf < 2; hf++) {
            const int row = m0 + wm + mt * 16 + g + hf * 8;
            const int c   = n0 + wn + nt * 8 + tg * 2;     // global col (even)
            float v0 = acc[mt][nt][hf * 2 + 0];
            float v1 = acc[mt][nt][hf * 2 + 1];
            if (c < HH) {
                v0 += __ldg(bm + c); v1 += __ldg(bm + c + 1);
                *(float2*)&g_med[(size_t)row * HH + c] = make_float2(v0, v1);
            } else if (c < NTOT) {
                const int nc = c - HH;
                v0 = softplusf(v0 + __ldg(bi + nc));
                v1 = softplusf(v1 + __ldg(bi + nc + 1));
                *(float2*)&g_inc[(size_t)row * NI + nc] = make_float2(v0, v1);
            }
        }
      }
    }
}

// ---------------------------------------------------------------------------
// Kernel 2: per-row quantile expansion as a tiny tf32 GEMM.
//   out[h][q] = sum_j A[h][j] * W[j][q],  A[h][0..10]=prefix, A[h][11]=median,
//   W[md[q]][q]=sg, W[10][q]=c1, W[11][q]=1, K padded to 16 with zeros.
// One block per batch row, 8 warps: 4 m-tiles(16) x 13 n-tiles(8), 2 k-steps.
// ---------------------------------------------------------------------------
#define ASTRD 20    // Ash row stride (floats): conflict-free frag loads
#define BSTRD 104   // Bsh row stride (floats)

__global__ __launch_bounds__(256) void out_kernel(const float* __restrict__ quant,
                                                  float* __restrict__ out) {
    __shared__ float qv[QQ], key_s[QQ];
    __shared__ int   rank_s[QQ];
    __shared__ float Ash[HH][ASTRD];     // cols 0..11 data, 12..15 zero
    __shared__ float Bsh[16][BSTRD];     // rows 12..15 & cols 99..103 stay zero
    __shared__ int   midx_s;

    const int b = blockIdx.x, tid = threadIdx.x;
    const int wid = tid >> 5, lane = tid & 31;

    if (tid < QQ) qv[tid] = quant[(size_t)b * QQ + tid];
    __syncthreads();

    // parallel phase: ranks | prefix matrix | zero B
    if (tid < QQ) {
        const float v = qv[tid];
        int r = 0;
        #pragma unroll 4
        for (int j = 0; j < QQ; j++) {
            const float u = qv[j];
            r += (u < v) || (u == v && j < tid);          // stable argsort rank
        }
        rank_s[tid] = r;
        key_s[tid]  = fabsf(v - 0.5f);
    } else if (tid >= 128 && tid < 192) {
        const int h = tid - 128;
        const float* ip = g_inc + (size_t)b * NI + h * 10;
        float s = 0.f;
        Ash[h][0] = 0.f;
        #pragma unroll
        for (int j = 0; j < 10; j++) { s += ip[j]; Ash[h][j + 1] = s; }
        Ash[h][11] = g_med[(size_t)b * HH + h];
        Ash[h][12] = 0.f; Ash[h][13] = 0.f; Ash[h][14] = 0.f; Ash[h][15] = 0.f;
    } else if (tid >= 192) {
        float* bz = &Bsh[0][0];
        for (int i = tid - 192; i < 16 * BSTRD; i += 64) bz[i] = 0.f;
    }
    __syncthreads();

    // m_idx: lexicographic min of (|q-0.5| bits, rank) via warp-0 reduction
    if (wid == 0) {
        unsigned long long best = ~0ull;
        for (int j = lane; j < QQ; j += 32) {
            unsigned long long code =
                ((unsigned long long)__float_as_uint(key_s[j]) << 32) | (unsigned)rank_s[j];
            best = best < code ? best : code;
        }
        #pragma unroll
        for (int o = 16; o; o >>= 1) {
            unsigned long long oth = __shfl_xor_sync(0xffffffff, best, o);
            best = best < oth ? best : oth;
        }
        if (lane == 0) midx_s = (int)(best & 0xffffffffu);
    }
    __syncthreads();

    // scatter the 3 nonzeros of each W column
    if (tid < QQ) {
        const int d  = rank_s[tid] - midx_s;
        const int st = d < 0 ? -d : d;
        const float sg = (float)((d > 0) - (d < 0));
        Bsh[st % 10][tid] = sg;
        Bsh[10][tid]      = sg * (float)(st / 10);
        Bsh[11][tid]      = 1.0f;
    }
    __syncthreads();

    // mma expansion: warp w -> m-tile (w&3); n-tiles split low/high
    const int mbase = (wid & 3) * 16;
    const int ntlo  = (wid < 4) ? 0 : 7;
    const int nthi  = (wid < 4) ? 7 : 13;
    const int g = lane >> 2, tg = lane & 3;

    uint32_t a[2][4];
    #pragma unroll
    for (int ks = 0; ks < 2; ks++) {
        const int k0 = ks * 8;
        a[ks][0] = f2tf(Ash[mbase + g    ][k0 + tg    ]);
        a[ks][1] = f2tf(Ash[mbase + g + 8][k0 + tg    ]);
        a[ks][2] = f2tf(Ash[mbase + g    ][k0 + tg + 4]);
        a[ks][3] = f2tf(Ash[mbase + g + 8][k0 + tg + 4]);
    }

    float* ob = out + (size_t)b * NOUT;
    for (int nt = ntlo; nt < nthi; nt++) {
        const int nbase = nt * 8;
        float c[4] = {0.f, 0.f, 0.f, 0.f};
        #pragma unroll
        for (int ks = 0; ks < 2; ks++) {
            uint32_t bb[2];
            bb[0] = __float_as_uint(Bsh[ks * 8 + tg    ][nbase + g]);
            bb[1] = __float_as_uint(Bsh[ks * 8 + tg + 4][nbase + g]);
            mma8(c, a[ks], bb);
        }
        const int q0 = nbase + tg * 2;
        const int r0 = mbase + g, r1 = r0 + 8;
        if (q0 < QQ) {
            ob[r0 * QQ + q0] = c[0];
            ob[r1 * QQ + q0] = c[2];
        }
        if (q0 + 1 < QQ) {
            ob[r0 * QQ + q0 + 1] = c[1];
            ob[r1 * QQ + q0 + 1] = c[3];
        }
    }
}

// ---------------------------------------------------------------------------
extern "C" void kernel_launch(void* const* d_in, const int* in_sizes, int n_in,
                              void* d_out, int out_size) {
    const float* x     = (const float*)d_in[0];
    const float* quant = (const float*)d_in[1];
    const float* Wm    = (const float*)d_in[2];
    const float* bm    = (const float*)d_in[3];
    const float* Wi    = (const float*)d_in[4];
    const float* bi    = (const float*)d_in[5];
    float* out = (float*)d_out;

    cudaFuncSetAttribute(gemm_kernel, cudaFuncAttributeMaxDynamicSharedMemorySize, SMEMSZ);

    cvt_x_kernel<<<(BROWS * HIDK) / (256 * 4), 256>>>(x);
    cvt_w_kernel<<<NTOTP, 256>>>(Wm, Wi);
    gemm_kernel<<<dim3(BROWS / BM, NTOTP / BN), 256, SMEMSZ>>>(bm, bi);
    out_kernel<<<BROWS, 256>>>(quant, out);
}

// round 9
// speedup vs baseline: 1.5299x; 1.5299x over previous
#include <cuda_runtime.h>
#include <cuda_bf16.h>
#include <math.h>
#include <stdint.h>

#define BROWS 8192
#define HIDK  1024
#define HH    64
#define QQ    99
#define NI    640
#define NTOT  704          // 64 + 640 output cols
#define NOUT  (HH*QQ)      // 6336

// ---------------- scratch (allocation-free rule: __device__ globals) -------
__device__ float          g_med[BROWS * HH];      // 2 MB
__device__ float          g_inc[BROWS * NI];      // 20 MB
__device__ __nv_bfloat16  g_xb [BROWS * HIDK];    // 16 MB  x in bf16
__device__ __nv_bfloat16  g_wt [NTOT  * HIDK];    // 1.4 MB [Wm|Wi]^T, n-major rows

// ---------------- helpers ---------------------------------------------------
__device__ __forceinline__ uint32_t smem_u32(const void* p) {
    uint32_t a;
    asm("{ .reg .u64 t; cvta.to.shared.u64 t, %1; cvt.u32.u64 %0, t; }" : "=r"(a) : "l"(p));
    return a;
}
__device__ __forceinline__ void cp_async16(uint32_t saddr, const void* gptr) {
    asm volatile("cp.async.cg.shared.global [%0], [%1], 16;" :: "r"(saddr), "l"(gptr));
}
__device__ __forceinline__ void cp_commit() { asm volatile("cp.async.commit_group;"); }
template <int N>
__device__ __forceinline__ void cp_wait() { asm volatile("cp.async.wait_group %0;" :: "n"(N)); }

__device__ __forceinline__ void ldmx4(uint32_t& r0, uint32_t& r1, uint32_t& r2, uint32_t& r3,
                                      uint32_t addr) {
    asm volatile("ldmatrix.sync.aligned.m8n8.x4.shared.b16 {%0,%1,%2,%3}, [%4];"
                 : "=r"(r0), "=r"(r1), "=r"(r2), "=r"(r3) : "r"(addr));
}
__device__ __forceinline__ void mma16(float c[4], const uint32_t a[4], const uint32_t b[2]) {
    asm volatile(
        "mma.sync.aligned.m16n8k16.row.col.f32.bf16.bf16.f32 "
        "{%0,%1,%2,%3}, {%4,%5,%6,%7}, {%8,%9}, {%0,%1,%2,%3};"
        : "+f"(c[0]), "+f"(c[1]), "+f"(c[2]), "+f"(c[3])
        : "r"(a[0]), "r"(a[1]), "r"(a[2]), "r"(a[3]), "r"(b[0]), "r"(b[1]));
}
__device__ __forceinline__ float softplusf(float v) {
    return fmaxf(v, 0.f) + log1pf(expf(-fabsf(v)));
}

// ---------------------------------------------------------------------------
// Prep: x (f32) -> g_xb (bf16)
// ---------------------------------------------------------------------------
__global__ __launch_bounds__(256) void cvt_x_kernel(const float* __restrict__ x) {
    const int i = blockIdx.x * 256 + threadIdx.x;          // float4 index
    float4 v = ((const float4*)x)[i];
    __nv_bfloat162 p0 = __floats2bfloat162_rn(v.x, v.y);
    __nv_bfloat162 p1 = __floats2bfloat162_rn(v.z, v.w);
    uint2 u;
    u.x = *(uint32_t*)&p0;
    u.y = *(uint32_t*)&p1;
    ((uint2*)g_xb)[i] = u;
}

// Prep: g_wt[n][k] = concat(Wm,Wi)^T as bf16 — 32x32 smem-tile transpose,
// coalesced on both the f32 read and the bf16 write.
// grid (NTOT/32, HIDK/32), block (32,8).
__global__ __launch_bounds__(256) void cvt_w_kernel(const float* __restrict__ Wm,
                                                    const float* __restrict__ Wi) {
    __shared__ float t[32][33];
    const int n0 = blockIdx.x * 32;
    const int k0 = blockIdx.y * 32;
    const int tx = threadIdx.x, ty = threadIdx.y;

    const float* src; int ld, c0;
    if (n0 < HH) { src = Wm; ld = HH; c0 = n0; } else { src = Wi; ld = NI; c0 = n0 - HH; }

    #pragma unroll
    for (int i = 0; i < 4; i++) {
        const int k = k0 + ty + i * 8;
        t[ty + i * 8][tx] = src[(size_t)k * ld + c0 + tx];       // row k, cols coalesced
    }
    __syncthreads();
    #pragma unroll
    for (int i = 0; i < 4; i++) {
        const int n = n0 + ty + i * 8;
        g_wt[(size_t)n * HIDK + k0 + tx] = __float2bfloat16(t[tx][ty + i * 8]);
    }
}

// ---------------------------------------------------------------------------
// Kernel 1: bf16 mma.sync m16n8k16 GEMM. Tile 128x64, BK=64, cp.async 2-stage.
// 8 warps as 4(m) x 2(n); warp tile 32x32. grid (11, 64): blockIdx.x = n-block
// (fastest-varying -> 11 concurrent CTAs share one A tile in L2),
// blockIdx.y = m-block. x==0 -> median cols (Wm), 1..10 -> 64-col block of Wi.
// ---------------------------------------------------------------------------
#define BM 128
#define BN 64
#define BK 64
#define ASTR 72                       // bf16 elems per smem row (+16B pad)
#define ABYTES (BM * ASTR * 2)        // 18432
#define BBYTES (BN * ASTR * 2)        // 9216
#define STAGE  (ABYTES + BBYTES)      // 27648
#define SMEMSZ (2 * STAGE)            // 55296
#define NKC (HIDK / BK)               // 16

__global__ __launch_bounds__(256) void gemm_kernel(const float* __restrict__ bm,
                                                   const float* __restrict__ bi) {
    extern __shared__ char sm[];
    const uint32_t smb = smem_u32(sm);

    const int tid  = threadIdx.x;
    const int wid  = tid >> 5, lane = tid & 31;
    const int by   = blockIdx.x;              // n-block role
    const int m0   = blockIdx.y * BM;
    const int n0   = by * BN;

    const int wm = (wid & 3) * 32;
    const int wn = (wid >> 2) * 32;

    const __nv_bfloat16* Abase = g_xb + (size_t)m0 * HIDK;
    const __nv_bfloat16* Bbase = g_wt + (size_t)n0 * HIDK;

    const int ar = tid >> 3, ac = (tid & 7) * 8;
    const int br = tid >> 3, bc = (tid & 7) * 8;

    float acc[2][4][4];
    #pragma unroll
    for (int mt = 0; mt < 2; mt++)
      #pragma unroll
      for (int nt = 0; nt < 4; nt++)
        #pragma unroll
        for (int i = 0; i < 4; i++) acc[mt][nt][i] = 0.f;

    const int quad = lane >> 3, rin = lane & 7;
    const int a_row = wm + rin + (quad & 1) * 8;
    const int a_kof = (quad >> 1) * 8;
    const int b_row = wn + rin + (quad >> 1) * 8;
    const int b_kof = (quad & 1) * 8;

    // prologue: stage chunk 0
    {
        #pragma unroll
        for (int i = 0; i < 4; i++)
            cp_async16(smb + (uint32_t)((ar + i * 32) * ASTR + ac) * 2,
                       Abase + (size_t)(ar + i * 32) * HIDK + ac);
        #pragma unroll
        for (int i = 0; i < 2; i++)
            cp_async16(smb + ABYTES + (uint32_t)((br + i * 32) * ASTR + bc) * 2,
                       Bbase + (size_t)(br + i * 32) * HIDK + bc);
        cp_commit();
    }

    for (int kc = 0; kc < NKC; kc++) {
        const int buf = kc & 1;
        const uint32_t sa  = smb + (buf ? STAGE : 0);
        const uint32_t sbB = sa + ABYTES;

        if (kc + 1 < NKC) {
            const uint32_t pa = smb + ((1 - buf) ? STAGE : 0);
            const __nv_bfloat16* Ag = Abase + (size_t)(kc + 1) * BK;
            const __nv_bfloat16* Bg = Bbase + (size_t)(kc + 1) * BK;
            #pragma unroll
            for (int i = 0; i < 4; i++)
                cp_async16(pa + (uint32_t)((ar + i * 32) * ASTR + ac) * 2,
                           Ag + (size_t)(ar + i * 32) * HIDK + ac);
            #pragma unroll
            for (int i = 0; i < 2; i++)
                cp_async16(pa + ABYTES + (uint32_t)((br + i * 32) * ASTR + bc) * 2,
                           Bg + (size_t)(br + i * 32) * HIDK + bc);
            cp_commit();
            cp_wait<1>();
        } else {
            cp_wait<0>();
        }
        __syncthreads();

        #pragma unroll
        for (int ks = 0; ks < 4; ks++) {
            uint32_t af[2][4], bf[2][4];
            #pragma unroll
            for (int mt = 0; mt < 2; mt++)
                ldmx4(af[mt][0], af[mt][1], af[mt][2], af[mt][3],
                      sa + (uint32_t)((a_row + mt * 16) * ASTR + ks * 16 + a_kof) * 2);
            #pragma unroll
            for (int p = 0; p < 2; p++)
                ldmx4(bf[p][0], bf[p][1], bf[p][2], bf[p][3],
                      sbB + (uint32_t)((b_row + p * 16) * ASTR + ks * 16 + b_kof) * 2);
            #pragma unroll
            for (int mt = 0; mt < 2; mt++)
              #pragma unroll
              for (int nt = 0; nt < 4; nt++)
                mma16(acc[mt][nt], af[mt], &bf[nt >> 1][(nt & 1) * 2]);
        }
        __syncthreads();
    }

    // epilogue: bias (+ softplus for inc part), float2 stores
    const int g = lane >> 2, tg = lane & 3;
    #pragma unroll
    for (int mt = 0; mt < 2; mt++) {
      #pragma unroll
      for (int nt = 0; nt < 4; nt++) {
        #pragma unroll
        for (int hf = 0; hf < 2; hf++) {
            const int row = m0 + wm + mt * 16 + g + hf * 8;
            const int col = wn + nt * 8 + tg * 2;
            float v0 = acc[mt][nt][hf * 2 + 0];
            float v1 = acc[mt][nt][hf * 2 + 1];
            if (by == 0) {
                v0 += __ldg(bm + col); v1 += __ldg(bm + col + 1);
                *(float2*)&g_med[(size_t)row * HH + col] = make_float2(v0, v1);
            } else {
                const int nc = (by - 1) * BN + col;
                v0 = softplusf(v0 + __ldg(bi + nc));
                v1 = softplusf(v1 + __ldg(bi + nc + 1));
                *(float2*)&g_inc[(size_t)row * NI + nc] = make_float2(v0, v1);
            }
        }
      }
    }
}

// ---------------------------------------------------------------------------
// Kernel 2: per-row quantile expansion. One block (224 thr) per batch row.
//   rank via packed u64 codes (bits(v)<<32 | idx): one cmp per candidate,
//   exactly reproduces stable argsort order (v >= 0 -> bits monotonic).
//   cum0(s) = (s/10)*P10 + prefix[s%10]  (pattern is 10-periodic)
//   out[b,h,q] = med[h] + sg_q*prefix[h][mod_q] + (sg_q*div_q)*P10[h]
// ph[h][0..10] = prefix, ph[h][11] = median
// ---------------------------------------------------------------------------
__global__ __launch_bounds__(224) void out_kernel(const float* __restrict__ quant,
                                                  float* __restrict__ out) {
    __shared__ unsigned long long code_s[QQ];
    __shared__ float key_s[QQ];
    __shared__ int   rank_s[QQ];
    __shared__ float sgn_s[QQ], c1_s[QQ];
    __shared__ int   mod_s[QQ];
    __shared__ float ph[HH][12];
    __shared__ int   midx_s;

    const int b = blockIdx.x, tid = threadIdx.x;
    const int wid = tid >> 5, lane = tid & 31;

    if (tid < QQ) {
        const float v = quant[(size_t)b * QQ + tid];
        code_s[tid] = ((unsigned long long)__float_as_uint(v) << 32) | (unsigned)tid;
        key_s[tid]  = fabsf(v - 0.5f);
    }
    __syncthreads();

    // parallel phase: ranks | prefix+median
    if (tid < QQ) {
        const unsigned long long my = code_s[tid];
        int r = 0;
        #pragma unroll 4
        for (int j = 0; j < QQ; j++) r += (code_s[j] < my);
        rank_s[tid] = r;
    } else if (tid >= 128 && tid < 192) {
        const int h = tid - 128;
        const float* ip = g_inc + (size_t)b * NI + h * 10;
        float s = 0.f;
        ph[h][0] = 0.f;
        #pragma unroll
        for (int j = 0; j < 10; j++) { s += ip[j]; ph[h][j + 1] = s; }
        ph[h][11] = g_med[(size_t)b * HH + h];
    }
    __syncthreads();

    // m_idx: lexicographic min of (|q-0.5| bits, rank) via warp-0 reduction
    if (wid == 0) {
        unsigned long long best = ~0ull;
        for (int j = lane; j < QQ; j += 32) {
            unsigned long long code =
                ((unsigned long long)__float_as_uint(key_s[j]) << 32) | (unsigned)rank_s[j];
            best = best < code ? best : code;
        }
        #pragma unroll
        for (int o = 16; o; o >>= 1) {
            unsigned long long oth = __shfl_xor_sync(0xffffffff, best, o);
            best = best < oth ? best : oth;
        }
        if (lane == 0) midx_s = (int)(best & 0xffffffffu);
    }
    __syncthreads();

    if (tid < QQ) {
        const int d  = rank_s[tid] - midx_s;
        const int st = d < 0 ? -d : d;
        const float sg = (float)((d > 0) - (d < 0));
        sgn_s[tid] = sg;
        c1_s[tid]  = sg * (float)(st / 10);
        mod_s[tid] = st % 10;
    }
    __syncthreads();

    if (tid < 198) {
        const int hl = (tid >= 99) ? 1 : 0;
        const int q0 = tid - hl * 99;
        const float sg = sgn_s[q0];
        const float c1 = c1_s[q0];
        const int   md = mod_s[q0];
        float* ob = out + (size_t)b * NOUT + hl * QQ + q0;
        #pragma unroll
        for (int hb = 0; hb < HH; hb += 2) {
            const int h = hb + hl;
            const float pv  = ph[h][md];
            const float p10 = ph[h][10];
            const float mv  = ph[h][11];
            ob[hb * QQ] = fmaf(c1, p10, fmaf(sg, pv, mv));
        }
    }
}

// ---------------------------------------------------------------------------
extern "C" void kernel_launch(void* const* d_in, const int* in_sizes, int n_in,
                              void* d_out, int out_size) {
    const float* x     = (const float*)d_in[0];
    const float* quant = (const float*)d_in[1];
    const float* Wm    = (const float*)d_in[2];
    const float* bm    = (const float*)d_in[3];
    const float* Wi    = (const float*)d_in[4];
    const float* bi    = (const float*)d_in[5];
    float* out = (float*)d_out;

    cudaFuncSetAttribute(gemm_kernel, cudaFuncAttributeMaxDynamicSharedMemorySize, SMEMSZ);

    cvt_x_kernel<<<(BROWS * HIDK) / (256 * 4), 256>>>(x);
    cvt_w_kernel<<<dim3(NTOT / 32, HIDK / 32), dim3(32, 8)>>>(Wm, Wi);
    gemm_kernel<<<dim3(11, BROWS / BM), 256, SMEMSZ>>>(bm, bi);
    out_kernel<<<BROWS, 224>>>(quant, out);
}

// round 10
// speedup vs baseline: 1.5328x; 1.0019x over previous
#include <cuda_runtime.h>
#include <cuda_bf16.h>
#include <math.h>
#include <stdint.h>

#define BROWS 8192
#define HIDK  1024
#define HH    64
#define QQ    99
#define NI    640
#define NTOT  704          // 64 + 640 output cols
#define NOUT  (HH*QQ)      // 6336

// ---------------- scratch (allocation-free rule: __device__ globals) -------
__device__ float          g_med[BROWS * HH];      // 2 MB
__device__ float          g_inc[BROWS * NI];      // 20 MB
__device__ __nv_bfloat16  g_xb [BROWS * HIDK];    // 16 MB  x in bf16
__device__ __nv_bfloat16  g_wt [NTOT  * HIDK];    // 1.4 MB [Wm|Wi]^T, n-major rows

// ---------------- helpers ---------------------------------------------------
__device__ __forceinline__ uint32_t smem_u32(const void* p) {
    uint32_t a;
    asm("{ .reg .u64 t; cvta.to.shared.u64 t, %1; cvt.u32.u64 %0, t; }" : "=r"(a) : "l"(p));
    return a;
}
__device__ __forceinline__ void cp_async16(uint32_t saddr, const void* gptr) {
    asm volatile("cp.async.cg.shared.global [%0], [%1], 16;" :: "r"(saddr), "l"(gptr));
}
__device__ __forceinline__ void cp_commit() { asm volatile("cp.async.commit_group;"); }
template <int N>
__device__ __forceinline__ void cp_wait() { asm volatile("cp.async.wait_group %0;" :: "n"(N)); }

__device__ __forceinline__ void ldmx4(uint32_t& r0, uint32_t& r1, uint32_t& r2, uint32_t& r3,
                                      uint32_t addr) {
    asm volatile("ldmatrix.sync.aligned.m8n8.x4.shared.b16 {%0,%1,%2,%3}, [%4];"
                 : "=r"(r0), "=r"(r1), "=r"(r2), "=r"(r3) : "r"(addr));
}
__device__ __forceinline__ void mma16(float c[4], const uint32_t a[4], const uint32_t b[2]) {
    asm volatile(
        "mma.sync.aligned.m16n8k16.row.col.f32.bf16.bf16.f32 "
        "{%0,%1,%2,%3}, {%4,%5,%6,%7}, {%8,%9}, {%0,%1,%2,%3};"
        : "+f"(c[0]), "+f"(c[1]), "+f"(c[2]), "+f"(c[3])
        : "r"(a[0]), "r"(a[1]), "r"(a[2]), "r"(a[3]), "r"(b[0]), "r"(b[1]));
}
__device__ __forceinline__ float softplusf(float v) {
    return fmaxf(v, 0.f) + log1pf(expf(-fabsf(v)));
}

// ---------------------------------------------------------------------------
// Prep: x (f32) -> g_xb (bf16)
// ---------------------------------------------------------------------------
__global__ __launch_bounds__(256) void cvt_x_kernel(const float* __restrict__ x) {
    const int i = blockIdx.x * 256 + threadIdx.x;          // float4 index
    float4 v = ((const float4*)x)[i];
    __nv_bfloat162 p0 = __floats2bfloat162_rn(v.x, v.y);
    __nv_bfloat162 p1 = __floats2bfloat162_rn(v.z, v.w);
    uint2 u;
    u.x = *(uint32_t*)&p0;
    u.y = *(uint32_t*)&p1;
    ((uint2*)g_xb)[i] = u;
}

// Prep: g_wt[n][k] = concat(Wm,Wi)^T as bf16 — 32x32 smem-tile transpose,
// coalesced on both the f32 read and the bf16 write.
// grid (NTOT/32, HIDK/32), block (32,8).
__global__ __launch_bounds__(256) void cvt_w_kernel(const float* __restrict__ Wm,
                                                    const float* __restrict__ Wi) {
    __shared__ float t[32][33];
    const int n0 = blockIdx.x * 32;
    const int k0 = blockIdx.y * 32;
    const int tx = threadIdx.x, ty = threadIdx.y;

    const float* src; int ld, c0;
    if (n0 < HH) { src = Wm; ld = HH; c0 = n0; } else { src = Wi; ld = NI; c0 = n0 - HH; }

    #pragma unroll
    for (int i = 0; i < 4; i++) {
        const int k = k0 + ty + i * 8;
        t[ty + i * 8][tx] = src[(size_t)k * ld + c0 + tx];       // row k, cols coalesced
    }
    __syncthreads();
    #pragma unroll
    for (int i = 0; i < 4; i++) {
        const int n = n0 + ty + i * 8;
        g_wt[(size_t)n * HIDK + k0 + tx] = __float2bfloat16(t[tx][ty + i * 8]);
    }
}

// ---------------------------------------------------------------------------
// Kernel 1: bf16 mma.sync m16n8k16 GEMM. Tile 128x64, BK=64, cp.async 2-stage.
// 8 warps as 4(m) x 2(n); warp tile 32x32. grid (11, 64): blockIdx.x = n-block
// (fastest-varying -> 11 concurrent CTAs share one A tile in L2),
// blockIdx.y = m-block. x==0 -> median cols (Wm), 1..10 -> 64-col block of Wi.
// ---------------------------------------------------------------------------
#define BM 128
#define BN 64
#define BK 64
#define ASTR 72                       // bf16 elems per smem row (+16B pad)
#define ABYTES (BM * ASTR * 2)        // 18432
#define BBYTES (BN * ASTR * 2)        // 9216
#define STAGE  (ABYTES + BBYTES)      // 27648
#define SMEMSZ (2 * STAGE)            // 55296
#define NKC (HIDK / BK)               // 16

__global__ __launch_bounds__(256) void gemm_kernel(const float* __restrict__ bm,
                                                   const float* __restrict__ bi) {
    extern __shared__ char sm[];
    const uint32_t smb = smem_u32(sm);

    const int tid  = threadIdx.x;
    const int wid  = tid >> 5, lane = tid & 31;
    const int by   = blockIdx.x;              // n-block role
    const int m0   = blockIdx.y * BM;
    const int n0   = by * BN;

    const int wm = (wid & 3) * 32;
    const int wn = (wid >> 2) * 32;

    const __nv_bfloat16* Abase = g_xb + (size_t)m0 * HIDK;
    const __nv_bfloat16* Bbase = g_wt + (size_t)n0 * HIDK;

    const int ar = tid >> 3, ac = (tid & 7) * 8;
    const int br = tid >> 3, bc = (tid & 7) * 8;

    float acc[2][4][4];
    #pragma unroll
    for (int mt = 0; mt < 2; mt++)
      #pragma unroll
      for (int nt = 0; nt < 4; nt++)
        #pragma unroll
        for (int i = 0; i < 4; i++) acc[mt][nt][i] = 0.f;

    const int quad = lane >> 3, rin = lane & 7;
    const int a_row = wm + rin + (quad & 1) * 8;
    const int a_kof = (quad >> 1) * 8;
    const int b_row = wn + rin + (quad >> 1) * 8;
    const int b_kof = (quad & 1) * 8;

    // prologue: stage chunk 0
    {
        #pragma unroll
        for (int i = 0; i < 4; i++)
            cp_async16(smb + (uint32_t)((ar + i * 32) * ASTR + ac) * 2,
                       Abase + (size_t)(ar + i * 32) * HIDK + ac);
        #pragma unroll
        for (int i = 0; i < 2; i++)
            cp_async16(smb + ABYTES + (uint32_t)((br + i * 32) * ASTR + bc) * 2,
                       Bbase + (size_t)(br + i * 32) * HIDK + bc);
        cp_commit();
    }

    for (int kc = 0; kc < NKC; kc++) {
        const int buf = kc & 1;
        const uint32_t sa  = smb + (buf ? STAGE : 0);
        const uint32_t sbB = sa + ABYTES;

        if (kc + 1 < NKC) {
            const uint32_t pa = smb + ((1 - buf) ? STAGE : 0);
            const __nv_bfloat16* Ag = Abase + (size_t)(kc + 1) * BK;
            const __nv_bfloat16* Bg = Bbase + (size_t)(kc + 1) * BK;
            #pragma unroll
            for (int i = 0; i < 4; i++)
                cp_async16(pa + (uint32_t)((ar + i * 32) * ASTR + ac) * 2,
                           Ag + (size_t)(ar + i * 32) * HIDK + ac);
            #pragma unroll
            for (int i = 0; i < 2; i++)
                cp_async16(pa + ABYTES + (uint32_t)((br + i * 32) * ASTR + bc) * 2,
                           Bg + (size_t)(br + i * 32) * HIDK + bc);
            cp_commit();
            cp_wait<1>();
        } else {
            cp_wait<0>();
        }
        __syncthreads();

        #pragma unroll
        for (int ks = 0; ks < 4; ks++) {
            uint32_t af[2][4], bf[2][4];
            #pragma unroll
            for (int mt = 0; mt < 2; mt++)
                ldmx4(af[mt][0], af[mt][1], af[mt][2], af[mt][3],
                      sa + (uint32_t)((a_row + mt * 16) * ASTR + ks * 16 + a_kof) * 2);
            #pragma unroll
            for (int p = 0; p < 2; p++)
                ldmx4(bf[p][0], bf[p][1], bf[p][2], bf[p][3],
                      sbB + (uint32_t)((b_row + p * 16) * ASTR + ks * 16 + b_kof) * 2);
            #pragma unroll
            for (int mt = 0; mt < 2; mt++)
              #pragma unroll
              for (int nt = 0; nt < 4; nt++)
                mma16(acc[mt][nt], af[mt], &bf[nt >> 1][(nt & 1) * 2]);
        }
        __syncthreads();
    }

    // epilogue: bias (+ softplus for inc part), float2 stores
    const int g = lane >> 2, tg = lane & 3;
    #pragma unroll
    for (int mt = 0; mt < 2; mt++) {
      #pragma unroll
      for (int nt = 0; nt < 4; nt++) {
        #pragma unroll
        for (int hf = 0; hf < 2; hf++) {
            const int row = m0 + wm + mt * 16 + g + hf * 8;
            const int col = wn + nt * 8 + tg * 2;
            float v0 = acc[mt][nt][hf * 2 + 0];
            float v1 = acc[mt][nt][hf * 2 + 1];
            if (by == 0) {
                v0 += __ldg(bm + col); v1 += __ldg(bm + col + 1);
                *(float2*)&g_med[(size_t)row * HH + col] = make_float2(v0, v1);
            } else {
                const int nc = (by - 1) * BN + col;
                v0 = softplusf(v0 + __ldg(bi + nc));
                v1 = softplusf(v1 + __ldg(bi + nc + 1));
                *(float2*)&g_inc[(size_t)row * NI + nc] = make_float2(v0, v1);
            }
        }
      }
    }
}

// ---------------------------------------------------------------------------
// Kernel 2: per-row quantile expansion. One block (224 thr) per batch row.
//   rank via packed u64 codes (bits(v)<<32 | idx): one cmp per candidate,
//   exactly reproduces stable argsort order (v >= 0 -> bits monotonic).
//   cum0(s) = (s/10)*P10 + prefix[s%10]  (pattern is 10-periodic)
//   out[b,h,q] = med[h] + sg_q*prefix[h][mod_q] + (sg_q*div_q)*P10[h]
// ph[h][0..10] = prefix, ph[h][11] = median
// ---------------------------------------------------------------------------
__global__ __launch_bounds__(224) void out_kernel(const float* __restrict__ quant,
                                                  float* __restrict__ out) {
    __shared__ unsigned long long code_s[QQ];
    __shared__ float key_s[QQ];
    __shared__ int   rank_s[QQ];
    __shared__ float sgn_s[QQ], c1_s[QQ];
    __shared__ int   mod_s[QQ];
    __shared__ float ph[HH][12];
    __shared__ int   midx_s;

    const int b = blockIdx.x, tid = threadIdx.x;
    const int wid = tid >> 5, lane = tid & 31;

    if (tid < QQ) {
        const float v = quant[(size_t)b * QQ + tid];
        code_s[tid] = ((unsigned long long)__float_as_uint(v) << 32) | (unsigned)tid;
        key_s[tid]  = fabsf(v - 0.5f);
    }
    __syncthreads();

    // parallel phase: ranks | prefix+median
    if (tid < QQ) {
        const unsigned long long my = code_s[tid];
        int r = 0;
        #pragma unroll 4
        for (int j = 0; j < QQ; j++) r += (code_s[j] < my);
        rank_s[tid] = r;
    } else if (tid >= 128 && tid < 192) {
        const int h = tid - 128;
        const float* ip = g_inc + (size_t)b * NI + h * 10;
        float s = 0.f;
        ph[h][0] = 0.f;
        #pragma unroll
        for (int j = 0; j < 10; j++) { s += ip[j]; ph[h][j + 1] = s; }
        ph[h][11] = g_med[(size_t)b * HH + h];
    }
    __syncthreads();

    // m_idx: lexicographic min of (|q-0.5| bits, rank) via warp-0 reduction
    if (wid == 0) {
        unsigned long long best = ~0ull;
        for (int j = lane; j < QQ; j += 32) {
            unsigned long long code =
                ((unsigned long long)__float_as_uint(key_s[j]) << 32) | (unsigned)rank_s[j];
            best = best < code ? best : code;
        }
        #pragma unroll
        for (int o = 16; o; o >>= 1) {
            unsigned long long oth = __shfl_xor_sync(0xffffffff, best, o);
            best = best < oth ? best : oth;
        }
        if (lane == 0) midx_s = (int)(best & 0xffffffffu);
    }
    __syncthreads();

    if (tid < QQ) {
        const int d  = rank_s[tid] - midx_s;
        const int st = d < 0 ? -d : d;
        const float sg = (float)((d > 0) - (d < 0));
        sgn_s[tid] = sg;
        c1_s[tid]  = sg * (float)(st / 10);
        mod_s[tid] = st % 10;
    }
    __syncthreads();

    if (tid < 198) {
        const int hl = (tid >= 99) ? 1 : 0;
        const int q0 = tid - hl * 99;
        const float sg = sgn_s[q0];
        const float c1 = c1_s[q0];
        const int   md = mod_s[q0];
        float* ob = out + (size_t)b * NOUT + hl * QQ + q0;
        #pragma unroll
        for (int hb = 0; hb < HH; hb += 2) {
            const int h = hb + hl;
            const float pv  = ph[h][md];
            const float p10 = ph[h][10];
            const float mv  = ph[h][11];
            ob[hb * QQ] = fmaf(c1, p10, fmaf(sg, pv, mv));
        }
    }
}

// ---------------------------------------------------------------------------
extern "C" void kernel_launch(void* const* d_in, const int* in_sizes, int n_in,
                              void* d_out, int out_size) {
    const float* x     = (const float*)d_in[0];
    const float* quant = (const float*)d_in[1];
    const float* Wm    = (const float*)d_in[2];
    const float* bm    = (const float*)d_in[3];
    const float* Wi    = (const float*)d_in[4];
    const float* bi    = (const float*)d_in[5];
    float* out = (float*)d_out;

    cudaFuncSetAttribute(gemm_kernel, cudaFuncAttributeMaxDynamicSharedMemorySize, SMEMSZ);

    cvt_x_kernel<<<(BROWS * HIDK) / (256 * 4), 256>>>(x);
    cvt_w_kernel<<<dim3(NTOT / 32, HIDK / 32), dim3(32, 8)>>>(Wm, Wi);
    gemm_kernel<<<dim3(11, BROWS / BM), 256, SMEMSZ>>>(bm, bi);
    out_kernel<<<BROWS, 224>>>(quant, out);
}